// round 9
// baseline (speedup 1.0000x reference)
#include <cuda_runtime.h>
#include <cuda_bf16.h>
#include <cstdint>

// data:  [B, C, N] fp32;  edges: [E, 2] int32
// out:   [B, C, N+E] fp32; head N cols zero, col N+e = (d[p0]+d[p1])*0.5
static constexpr int B_   = 4;
static constexpr int C_   = 128;
static constexpr int N_   = 100000;     // 32 * 3125
static constexpr int E_   = 200000;
static constexpr int BC_  = B_ * C_;    // 512
static constexpr int M_   = N_ + E_;    // 300000
static constexpr int N4_  = N_ / 4;     // 25000
static constexpr int M4_  = M_ / 4;     // 75000
static constexpr int BC4_ = BC_ / 4;    // 128

// Scratch: transposed data [N][BC] fp32 (205 MB)
__device__ float g_dataT[(size_t)N_ * BC_];

// ---------------------------------------------------------------------------
// Kernel 1: transpose data [BC, N] -> dataT [N, BC].  (measured at BW roofline)
// ---------------------------------------------------------------------------
__global__ __launch_bounds__(256)
void transpose_kernel(const float* __restrict__ data) {
    __shared__ float tile[128][33];
    const int n0  = blockIdx.x * 32;
    const int bc0 = blockIdx.y * 128;
    const int tx  = threadIdx.x & 31;
    const int r0  = threadIdx.x >> 5;

    #pragma unroll
    for (int k = 0; k < 16; ++k) {
        const int row = k * 8 + r0;
        tile[row][tx] = __ldg(&data[(size_t)(bc0 + row) * N_ + n0 + tx]);
    }
    __syncthreads();

    const int w  = threadIdx.x >> 5;
    const int l  = threadIdx.x & 31;
    const int nl = w * 4 + (l >> 3);
    const int c8 = l & 7;
    float4* __restrict__ dT4 = reinterpret_cast<float4*>(g_dataT);
    #pragma unroll
    for (int i = 0; i < 4; ++i) {
        const int c4 = c8 + 8 * i;
        float4 v;
        v.x = tile[4 * c4 + 0][nl];
        v.y = tile[4 * c4 + 1][nl];
        v.z = tile[4 * c4 + 2][nl];
        v.w = tile[4 * c4 + 3][nl];
        // default caching: gather kernel re-reads dataT, keep it in L2
        dT4[(size_t)(n0 + nl) * BC4_ + (bc0 >> 2) + c4] = v;
    }
}

// ---------------------------------------------------------------------------
// Kernel 2: fused zero-head + gather. CTA = 32 edges, 512 threads.
// All output stores use __stcs (streaming) so the 615 MB write stream does
// not evict dataT from L2 (dataT reuse ~4x is the only L2-exploitable reuse).
// ---------------------------------------------------------------------------
static constexpr int TILE_E = 32;

__global__ __launch_bounds__(512)
void gather_mid_kernel(const int* __restrict__ edges,
                       float*     __restrict__ out) {
    __shared__ float mid[TILE_E * BC_];      // 64 KB, XOR-swizzled
    __shared__ int   sedge[TILE_E * 2];

    const int t  = threadIdx.x;
    const int e0 = blockIdx.x * TILE_E;

    // ---- fused zero head (streaming stores) ----
    {
        const float4 z = make_float4(0.f, 0.f, 0.f, 0.f);
        float4* __restrict__ o4 = reinterpret_cast<float4*>(out);
        #pragma unroll
        for (int k = 0; k < 4; ++k) {
            const int idx = blockIdx.x * 2048 + k * 512 + t;
            const int bc  = idx / N4_;
            const int j4  = idx - bc * N4_;
            __stcs(&o4[(size_t)bc * M4_ + j4], z);
        }
    }

    if (t < TILE_E * 2) sedge[t] = __ldg(&edges[e0 * 2 + t]);
    __syncthreads();

    // ---- phase A: float4 gather-average in transposed space ----
    const int q = t >> 7;                    // edge slot 0..3
    const int m = t & 127;                   // bc float4 index
    const float4* __restrict__ dT4 = reinterpret_cast<const float4*>(g_dataT);
    float4* __restrict__ mid4 = reinterpret_cast<float4*>(mid);

    #pragma unroll 4
    for (int it = 0; it < 8; ++it) {
        const int el = it * 4 + q;
        const int p0 = sedge[2 * el];
        const int p1 = sedge[2 * el + 1];
        const float4 a = __ldg(&dT4[(size_t)p0 * BC4_ + m]);
        const float4 b = __ldg(&dT4[(size_t)p1 * BC4_ + m]);
        float4 r;
        r.x = (a.x + b.x) * 0.5f;
        r.y = (a.y + b.y) * 0.5f;
        r.z = (a.z + b.z) * 0.5f;
        r.w = (a.w + b.w) * 0.5f;
        mid4[el * BC4_ + (m ^ (el >> 2))] = r;   // conflict-free swizzle
    }
    __syncthreads();

    // ---- phase B: transpose-on-write, 128B coalesced streaming stores ----
    const int w = t >> 5;
    const int l = t & 31;
    const int j = l & 7;
    #pragma unroll
    for (int iter = 0; iter < BC_ / 64; ++iter) {
        const int bc = iter * 64 + w * 4 + (l >> 3);
        const int c4 = bc >> 2;
        const int b3 = bc & 3;
        float4 r;
        r.x = mid[(4 * j + 0) * BC_ + 4 * (c4 ^ j) + b3];
        r.y = mid[(4 * j + 1) * BC_ + 4 * (c4 ^ j) + b3];
        r.z = mid[(4 * j + 2) * BC_ + 4 * (c4 ^ j) + b3];
        r.w = mid[(4 * j + 3) * BC_ + 4 * (c4 ^ j) + b3];
        float4* __restrict__ dst =
            reinterpret_cast<float4*>(out + (size_t)bc * M_);
        __stcs(&dst[N4_ + (e0 >> 2) + j], r);
    }
}

extern "C" void kernel_launch(void* const* d_in, const int* in_sizes, int n_in,
                              void* d_out, int out_size) {
    const float* data  = (const float*)d_in[0];
    const int*   edges = (const int*)d_in[1];
    float*       out   = (float*)d_out;

    transpose_kernel<<<dim3(N_ / 32, BC_ / 128), 256>>>(data);
    gather_mid_kernel<<<E_ / TILE_E, 512>>>(edges, out);
}

// round 10
// speedup vs baseline: 1.2043x; 1.2043x over previous
#include <cuda_runtime.h>
#include <cuda_bf16.h>
#include <cstdint>

// data:  [B, C, N] fp32;  edges: [E, 2] int32
// out:   [B, C, N+E] fp32; head N cols zero, col N+e = (d[p0]+d[p1])*0.5
static constexpr int B_    = 4;
static constexpr int C_    = 128;
static constexpr int N_    = 100000;    // 32 * 3125
static constexpr int E_    = 200000;
static constexpr int BC_   = B_ * C_;   // 512
static constexpr int M_    = N_ + E_;   // 300000
static constexpr int N4_   = N_ / 4;    // 25000
static constexpr int M4_   = M_ / 4;    // 75000

static constexpr int BCP_  = 128;       // bc channels per pass
static constexpr int BCP4_ = BCP_ / 4;  // 32
static constexpr int NPASS = BC_ / BCP_;// 4
static constexpr int TILE_E = 64;       // edges per gather CTA

// Scratch: transposed slice [N][128] fp32 = 51.2 MB — sized to stay L2-resident.
// Reused by all 4 passes (overwrite-while-dirty => no DRAM writeback).
__device__ float g_dataT[(size_t)N_ * BCP_];

// ---------------------------------------------------------------------------
// Kernel 1: transpose one bc-slice: data[bc0..bc0+127][N] -> g_dataT[N][128].
// grid 3125, block 256. Reads 128B coalesced; writes 512B rows (float4).
// ---------------------------------------------------------------------------
__global__ __launch_bounds__(256)
void transpose_kernel(const float* __restrict__ data, int bc0) {
    __shared__ float tile[128][33];
    const int n0 = blockIdx.x * 32;
    const int tx = threadIdx.x & 31;
    const int r0 = threadIdx.x >> 5;

    #pragma unroll
    for (int k = 0; k < 16; ++k) {
        const int row = k * 8 + r0;                 // bc within slice
        tile[row][tx] = __ldg(&data[(size_t)(bc0 + row) * N_ + n0 + tx]);
    }
    __syncthreads();

    const int w  = threadIdx.x >> 5;
    const int l  = threadIdx.x & 31;
    const int nl = w * 4 + (l >> 3);                // n within tile, 0..31
    const int c8 = l & 7;
    float4* __restrict__ dT4 = reinterpret_cast<float4*>(g_dataT);
    #pragma unroll
    for (int i = 0; i < 4; ++i) {
        const int c4 = c8 + 8 * i;                  // bc float4, 0..31
        float4 v;
        v.x = tile[4 * c4 + 0][nl];
        v.y = tile[4 * c4 + 1][nl];
        v.z = tile[4 * c4 + 2][nl];
        v.w = tile[4 * c4 + 3][nl];
        dT4[(size_t)(n0 + nl) * BCP4_ + c4] = v;    // stays hot in L2
    }
}

// ---------------------------------------------------------------------------
// Kernel 2: fused zero-head + gather for one bc-slice. CTA = 64 edges, 512 thr.
// SMEM mid float (el, bc): word = el*128 + 4*((bc>>2) ^ (el>>2)) + (bc&3).
//   Phase A float4 stores and phase B column reads are both conflict-free.
// Output stores streamed (__stcs) so they don't displace the L2 scratch.
// ---------------------------------------------------------------------------
__global__ __launch_bounds__(512)
void gather_mid_kernel(const int* __restrict__ edges,
                       float*     __restrict__ out, int bc0) {
    __shared__ float mid[TILE_E * BCP_];            // 32 KB
    __shared__ int   sedge[TILE_E * 2];

    const int t  = threadIdx.x;
    const int e0 = blockIdx.x * TILE_E;

    // ---- fused zero head: 128 rows * 25000 float4 = 3.2M over 3125 CTAs ----
    {
        const float4 z = make_float4(0.f, 0.f, 0.f, 0.f);
        float4* __restrict__ o4 = reinterpret_cast<float4*>(out);
        #pragma unroll
        for (int k = 0; k < 2; ++k) {
            const int idx = blockIdx.x * 1024 + k * 512 + t;
            const int bcl = idx / N4_;
            const int j4  = idx - bcl * N4_;
            __stcs(&o4[(size_t)(bc0 + bcl) * M4_ + j4], z);
        }
    }

    if (t < TILE_E * 2) sedge[t] = __ldg(&edges[e0 * 2 + t]);
    __syncthreads();

    // ---- phase A: float4 gather-average from L2-resident scratch ----
    const int q = t >> 5;                           // edge slot 0..15
    const int m = t & 31;                           // bc float4 0..31
    const float4* __restrict__ dT4 = reinterpret_cast<const float4*>(g_dataT);
    float4* __restrict__ mid4 = reinterpret_cast<float4*>(mid);

    #pragma unroll
    for (int it = 0; it < 4; ++it) {
        const int el = it * 16 + q;
        const int p0 = sedge[2 * el];
        const int p1 = sedge[2 * el + 1];
        const float4 a = __ldg(&dT4[(size_t)p0 * BCP4_ + m]);
        const float4 b = __ldg(&dT4[(size_t)p1 * BCP4_ + m]);
        float4 r;
        r.x = (a.x + b.x) * 0.5f;
        r.y = (a.y + b.y) * 0.5f;
        r.z = (a.z + b.z) * 0.5f;
        r.w = (a.w + b.w) * 0.5f;
        mid4[el * BCP4_ + (m ^ (el >> 2))] = r;     // conflict-free swizzle
    }
    __syncthreads();

    // ---- phase B: transpose-on-write, 128B coalesced streaming stores ----
    const int w = t >> 5;
    const int l = t & 31;
    const int j = l & 7;
    #pragma unroll
    for (int iter = 0; iter < 2; ++iter) {
        const int bcl = iter * 64 + w * 4 + (l >> 3);   // 0..127
        const int c4  = bcl >> 2;
        const int b3  = bcl & 3;
        float4* __restrict__ dst =
            reinterpret_cast<float4*>(out + (size_t)(bc0 + bcl) * M_);
        #pragma unroll
        for (int h = 0; h < 2; ++h) {
            const int jj = j + 8 * h;                   // float4 span 0..15
            float4 r;
            r.x = mid[(4 * jj + 0) * BCP_ + 4 * (c4 ^ jj) + b3];
            r.y = mid[(4 * jj + 1) * BCP_ + 4 * (c4 ^ jj) + b3];
            r.z = mid[(4 * jj + 2) * BCP_ + 4 * (c4 ^ jj) + b3];
            r.w = mid[(4 * jj + 3) * BCP_ + 4 * (c4 ^ jj) + b3];
            __stcs(&dst[N4_ + (e0 >> 2) + jj], r);
        }
    }
}

extern "C" void kernel_launch(void* const* d_in, const int* in_sizes, int n_in,
                              void* d_out, int out_size) {
    const float* data  = (const float*)d_in[0];
    const int*   edges = (const int*)d_in[1];
    float*       out   = (float*)d_out;

    for (int p = 0; p < NPASS; ++p) {
        const int bc0 = p * BCP_;
        transpose_kernel<<<N_ / 32, 256>>>(data, bc0);
        gather_mid_kernel<<<E_ / TILE_E, 512>>>(edges, out, bc0);
    }
}

// round 11
// speedup vs baseline: 1.2047x; 1.0003x over previous
#include <cuda_runtime.h>
#include <cuda_bf16.h>
#include <cstdint>

// data:  [B, C, N] fp32;  edges: [E, 2] int32
// out:   [B, C, N+E] fp32; head N cols zero, col N+e = (d[p0]+d[p1])*0.5
static constexpr int B_    = 4;
static constexpr int C_    = 128;
static constexpr int N_    = 100000;    // 32 * 3125
static constexpr int E_    = 200000;
static constexpr int BC_   = B_ * C_;   // 512
static constexpr int M_    = N_ + E_;   // 300000
static constexpr int N4_   = N_ / 4;    // 25000
static constexpr int M4_   = M_ / 4;    // 75000

static constexpr int BCP_  = 128;       // bc channels per pass
static constexpr int BCP4_ = BCP_ / 4;  // 32
static constexpr int NPASS = BC_ / BCP_;// 4
static constexpr int TILE_E = 64;       // edges per gather CTA

// Scratch: transposed slice [N][128] fp32 = 51.2 MB — sized to stay L2-resident.
// Reused by all 4 passes (overwrite-while-dirty => no DRAM writeback).
__device__ float g_dataT[(size_t)N_ * BCP_];

// ---------------------------------------------------------------------------
// Kernel 1: transpose one bc-slice: data[bc0..bc0+127][N] -> g_dataT[N][128].
// grid 3125, block 256. Reads 128B coalesced; writes 512B rows (float4).
// ---------------------------------------------------------------------------
__global__ __launch_bounds__(256)
void transpose_kernel(const float* __restrict__ data, int bc0) {
    __shared__ float tile[128][33];
    const int n0 = blockIdx.x * 32;
    const int tx = threadIdx.x & 31;
    const int r0 = threadIdx.x >> 5;

    #pragma unroll
    for (int k = 0; k < 16; ++k) {
        const int row = k * 8 + r0;                 // bc within slice
        tile[row][tx] = __ldg(&data[(size_t)(bc0 + row) * N_ + n0 + tx]);
    }
    __syncthreads();

    const int w  = threadIdx.x >> 5;
    const int l  = threadIdx.x & 31;
    const int nl = w * 4 + (l >> 3);                // n within tile, 0..31
    const int c8 = l & 7;
    float4* __restrict__ dT4 = reinterpret_cast<float4*>(g_dataT);
    #pragma unroll
    for (int i = 0; i < 4; ++i) {
        const int c4 = c8 + 8 * i;                  // bc float4, 0..31
        float4 v;
        v.x = tile[4 * c4 + 0][nl];
        v.y = tile[4 * c4 + 1][nl];
        v.z = tile[4 * c4 + 2][nl];
        v.w = tile[4 * c4 + 3][nl];
        dT4[(size_t)(n0 + nl) * BCP4_ + c4] = v;    // stays hot in L2
    }
}

// ---------------------------------------------------------------------------
// Kernel 2: fused zero-head + gather for one bc-slice. CTA = 64 edges, 512 thr.
// SMEM mid float (el, bc): word = el*128 + 4*((bc>>2) ^ (el>>2)) + (bc&3).
//   Phase A float4 stores and phase B column reads are both conflict-free.
// Output stores streamed (__stcs) so they don't displace the L2 scratch.
// ---------------------------------------------------------------------------
__global__ __launch_bounds__(512)
void gather_mid_kernel(const int* __restrict__ edges,
                       float*     __restrict__ out, int bc0) {
    __shared__ float mid[TILE_E * BCP_];            // 32 KB
    __shared__ int   sedge[TILE_E * 2];

    const int t  = threadIdx.x;
    const int e0 = blockIdx.x * TILE_E;

    // ---- fused zero head: 128 rows * 25000 float4 = 3.2M over 3125 CTAs ----
    {
        const float4 z = make_float4(0.f, 0.f, 0.f, 0.f);
        float4* __restrict__ o4 = reinterpret_cast<float4*>(out);
        #pragma unroll
        for (int k = 0; k < 2; ++k) {
            const int idx = blockIdx.x * 1024 + k * 512 + t;
            const int bcl = idx / N4_;
            const int j4  = idx - bcl * N4_;
            __stcs(&o4[(size_t)(bc0 + bcl) * M4_ + j4], z);
        }
    }

    if (t < TILE_E * 2) sedge[t] = __ldg(&edges[e0 * 2 + t]);
    __syncthreads();

    // ---- phase A: float4 gather-average from L2-resident scratch ----
    const int q = t >> 5;                           // edge slot 0..15
    const int m = t & 31;                           // bc float4 0..31
    const float4* __restrict__ dT4 = reinterpret_cast<const float4*>(g_dataT);
    float4* __restrict__ mid4 = reinterpret_cast<float4*>(mid);

    #pragma unroll
    for (int it = 0; it < 4; ++it) {
        const int el = it * 16 + q;
        const int p0 = sedge[2 * el];
        const int p1 = sedge[2 * el + 1];
        const float4 a = __ldg(&dT4[(size_t)p0 * BCP4_ + m]);
        const float4 b = __ldg(&dT4[(size_t)p1 * BCP4_ + m]);
        float4 r;
        r.x = (a.x + b.x) * 0.5f;
        r.y = (a.y + b.y) * 0.5f;
        r.z = (a.z + b.z) * 0.5f;
        r.w = (a.w + b.w) * 0.5f;
        mid4[el * BCP4_ + (m ^ (el >> 2))] = r;     // conflict-free swizzle
    }
    __syncthreads();

    // ---- phase B: transpose-on-write, 128B coalesced streaming stores ----
    const int w = t >> 5;
    const int l = t & 31;
    const int j = l & 7;
    #pragma unroll
    for (int iter = 0; iter < 2; ++iter) {
        const int bcl = iter * 64 + w * 4 + (l >> 3);   // 0..127
        const int c4  = bcl >> 2;
        const int b3  = bcl & 3;
        float4* __restrict__ dst =
            reinterpret_cast<float4*>(out + (size_t)(bc0 + bcl) * M_);
        #pragma unroll
        for (int h = 0; h < 2; ++h) {
            const int jj = j + 8 * h;                   // float4 span 0..15
            float4 r;
            r.x = mid[(4 * jj + 0) * BCP_ + 4 * (c4 ^ jj) + b3];
            r.y = mid[(4 * jj + 1) * BCP_ + 4 * (c4 ^ jj) + b3];
            r.z = mid[(4 * jj + 2) * BCP_ + 4 * (c4 ^ jj) + b3];
            r.w = mid[(4 * jj + 3) * BCP_ + 4 * (c4 ^ jj) + b3];
            __stcs(&dst[N4_ + (e0 >> 2) + jj], r);
        }
    }
}

extern "C" void kernel_launch(void* const* d_in, const int* in_sizes, int n_in,
                              void* d_out, int out_size) {
    const float* data  = (const float*)d_in[0];
    const int*   edges = (const int*)d_in[1];
    float*       out   = (float*)d_out;

    for (int p = 0; p < NPASS; ++p) {
        const int bc0 = p * BCP_;
        transpose_kernel<<<N_ / 32, 256>>>(data, bc0);
        gather_mid_kernel<<<E_ / TILE_E, 512>>>(edges, out, bc0);
    }
}

// round 12
// speedup vs baseline: 1.2357x; 1.0258x over previous
#include <cuda_runtime.h>
#include <cuda_bf16.h>
#include <cstdint>

// data:  [B, C, N] fp32;  edges: [E, 2] int32
// out:   [B, C, N+E] fp32; head N cols zero, col N+e = (d[p0]+d[p1])*0.5
static constexpr int B_    = 4;
static constexpr int C_    = 128;
static constexpr int N_    = 100000;    // 32 * 3125
static constexpr int E_    = 200000;
static constexpr int BC_   = B_ * C_;   // 512
static constexpr int M_    = N_ + E_;   // 300000
static constexpr int N4_   = N_ / 4;    // 25000
static constexpr int M4_   = M_ / 4;    // 75000

static constexpr int BCP_  = 128;       // bc channels per pass
static constexpr int BCP4_ = BCP_ / 4;  // 32
static constexpr int NPASS = BC_ / BCP_;// 4
static constexpr int TILE_E  = 64;      // edges per gather CTA
static constexpr int NGTILE  = E_ / TILE_E;   // 3125 gather CTAs
static constexpr int NTTILE  = N_ / 32;       // 3125 transpose CTAs

// Double-buffered transposed slice [N][128] fp32, 51.2 MB each.
__device__ float g_scratch[2][(size_t)N_ * BCP_];

// ---------------------------------------------------------------------------
// Transpose role (512 threads): data[bc0..bc0+127][n0..n0+31] -> buf[N][128]
// ---------------------------------------------------------------------------
__device__ __forceinline__
void transpose_role(const float* __restrict__ data, float* __restrict__ buf,
                    int bc0, int tileIdx, float (*tile)[33]) {
    const int n0 = tileIdx * 32;
    const int t  = threadIdx.x;
    const int tx = t & 31;
    const int wp = t >> 5;                       // 0..15

    #pragma unroll
    for (int k = 0; k < 8; ++k) {
        const int row = k * 16 + wp;             // bc within slice, 0..127
        tile[row][tx] = __ldcs(&data[(size_t)(bc0 + row) * N_ + n0 + tx]);
    }
    __syncthreads();

    const int l  = t & 31;
    const int nl = (wp & 7) * 4 + (l >> 3);      // n within tile, 0..31
    const int i2 = (wp >> 3) * 2;                // split c4-iters across warp halves
    float4* __restrict__ b4 = reinterpret_cast<float4*>(buf);
    #pragma unroll
    for (int ii = 0; ii < 2; ++ii) {
        const int c4 = (l & 7) + 8 * (i2 + ii);  // bc float4, 0..31
        float4 v;
        v.x = tile[4 * c4 + 0][nl];
        v.y = tile[4 * c4 + 1][nl];
        v.z = tile[4 * c4 + 2][nl];
        v.w = tile[4 * c4 + 3][nl];
        b4[(size_t)(n0 + nl) * BCP4_ + c4] = v;  // keep hot in L2
    }
}

// ---------------------------------------------------------------------------
// Gather role (512 threads): zero-head chunk + 64-edge tile for one bc slice.
// ---------------------------------------------------------------------------
__device__ __forceinline__
void gather_role(const int* __restrict__ edges, float* __restrict__ out,
                 const float* __restrict__ buf, int bc0, int tileIdx,
                 float* mid, int* sedge) {
    const int t  = threadIdx.x;
    const int e0 = tileIdx * TILE_E;

    // fused zero head: 128 rows * 25000 float4 over 3125 tiles
    {
        const float4 z = make_float4(0.f, 0.f, 0.f, 0.f);
        float4* __restrict__ o4 = reinterpret_cast<float4*>(out);
        #pragma unroll
        for (int k = 0; k < 2; ++k) {
            const int idx = tileIdx * 1024 + k * 512 + t;
            const int bcl = idx / N4_;
            const int j4  = idx - bcl * N4_;
            __stcs(&o4[(size_t)(bc0 + bcl) * M4_ + j4], z);
        }
    }

    if (t < TILE_E * 2) sedge[t] = __ldg(&edges[e0 * 2 + t]);
    __syncthreads();

    // phase A: float4 gather-average from L2-resident scratch
    const int q = t >> 5;                        // edge slot 0..15
    const int m = t & 31;                        // bc float4 0..31
    const float4* __restrict__ dT4 = reinterpret_cast<const float4*>(buf);
    float4* __restrict__ mid4 = reinterpret_cast<float4*>(mid);

    #pragma unroll
    for (int it = 0; it < 4; ++it) {
        const int el = it * 16 + q;
        const int p0 = sedge[2 * el];
        const int p1 = sedge[2 * el + 1];
        const float4 a = __ldg(&dT4[(size_t)p0 * BCP4_ + m]);
        const float4 b = __ldg(&dT4[(size_t)p1 * BCP4_ + m]);
        float4 r;
        r.x = (a.x + b.x) * 0.5f;
        r.y = (a.y + b.y) * 0.5f;
        r.z = (a.z + b.z) * 0.5f;
        r.w = (a.w + b.w) * 0.5f;
        mid4[el * BCP4_ + (m ^ (el >> 2))] = r;  // conflict-free swizzle
    }
    __syncthreads();

    // phase B: transpose-on-write, 128B coalesced streaming stores
    const int w = t >> 5;
    const int l = t & 31;
    const int j = l & 7;
    #pragma unroll
    for (int iter = 0; iter < 2; ++iter) {
        const int bcl = iter * 64 + w * 4 + (l >> 3);
        const int c4  = bcl >> 2;
        const int b3  = bcl & 3;
        float4* __restrict__ dst =
            reinterpret_cast<float4*>(out + (size_t)(bc0 + bcl) * M_);
        #pragma unroll
        for (int h = 0; h < 2; ++h) {
            const int jj = j + 8 * h;
            float4 r;
            r.x = mid[(4 * jj + 0) * BCP_ + 4 * (c4 ^ jj) + b3];
            r.y = mid[(4 * jj + 1) * BCP_ + 4 * (c4 ^ jj) + b3];
            r.z = mid[(4 * jj + 2) * BCP_ + 4 * (c4 ^ jj) + b3];
            r.w = mid[(4 * jj + 3) * BCP_ + 4 * (c4 ^ jj) + b3];
            __stcs(&dst[N4_ + (e0 >> 2) + jj], r);
        }
    }
}

// ---------------------------------------------------------------------------
// Fused pipelined kernel: CTAs [0, nGather) gather slice from bufG;
// CTAs [nGather, nGather+nTrans) transpose next slice into bufT.
// smem for both roles is statically allocated (~49.4 KB total) -> 4 CTA/SM.
// ---------------------------------------------------------------------------
__global__ __launch_bounds__(512)
void fused_kernel(const float* __restrict__ data,
                  const int*   __restrict__ edges,
                  float*       __restrict__ out,
                  int nGather, int gat_bc0, int bufG_idx,
                  int trn_bc0, int bufT_idx) {
    __shared__ float tile[128][33];              // transpose role
    __shared__ float mid[TILE_E * BCP_];         // gather role (32 KB)
    __shared__ int   sedge[TILE_E * 2];

    if ((int)blockIdx.x < nGather) {
        gather_role(edges, out, g_scratch[bufG_idx], gat_bc0,
                    blockIdx.x, mid, sedge);
    } else {
        transpose_role(data, g_scratch[bufT_idx], trn_bc0,
                       blockIdx.x - nGather, tile);
    }
}

extern "C" void kernel_launch(void* const* d_in, const int* in_sizes, int n_in,
                              void* d_out, int out_size) {
    const float* data  = (const float*)d_in[0];
    const int*   edges = (const int*)d_in[1];
    float*       out   = (float*)d_out;

    // Prologue: transpose slice 0 -> buf0 (no gather yet)
    fused_kernel<<<NTTILE, 512>>>(data, edges, out,
                                  /*nGather=*/0, 0, 0,
                                  /*trn_bc0=*/0, /*bufT=*/0);
    // Pipelined passes 0..2: gather slice p + transpose slice p+1
    for (int p = 0; p < NPASS - 1; ++p) {
        fused_kernel<<<NGTILE + NTTILE, 512>>>(data, edges, out,
                                               NGTILE, p * BCP_, p & 1,
                                               (p + 1) * BCP_, (p + 1) & 1);
    }
    // Epilogue: gather slice 3 only
    fused_kernel<<<NGTILE, 512>>>(data, edges, out,
                                  NGTILE, (NPASS - 1) * BCP_, (NPASS - 1) & 1,
                                  0, 0);
}

// round 13
// speedup vs baseline: 1.2983x; 1.0507x over previous
#include <cuda_runtime.h>
#include <cuda_bf16.h>
#include <cstdint>

// data:  [B, C, N] fp32;  edges: [E, 2] int32
// out:   [B, C, N+E] fp32; head N cols zero, col N+e = (d[p0]+d[p1])*0.5
static constexpr int B_    = 4;
static constexpr int C_    = 128;
static constexpr int N_    = 100000;     // 64 * 1562.5 -> use N_/64 = 1562.5? no: 100000/64 = 1562.5
static constexpr int E_    = 200000;
static constexpr int BC_   = B_ * C_;    // 512
static constexpr int M_    = N_ + E_;    // 300000
static constexpr int N4_   = N_ / 4;     // 25000
static constexpr int M4_   = M_ / 4;     // 75000

static constexpr int BCP_   = 64;        // bc channels per pass
static constexpr int BCP4_  = BCP_ / 4;  // 16
static constexpr int NPASS  = BC_ / BCP_;// 8
static constexpr int TILE_E = 128;       // edges per gather CTA
static constexpr int NGTILE = (E_ + TILE_E - 1) / TILE_E;  // 1563 (last CTA: 64 edges)
static constexpr int TILE_N = 32;        // n-cols per transpose CTA (N_ % 32 == 0)
static constexpr int NTTILE = N_ / TILE_N;                 // 3125

// Double-buffered transposed slice [N][64] fp32, 25.6 MB each (51.2 MB total:
// the footprint proven fully L2-resident in round 11).
__device__ float g_scratch[2][(size_t)N_ * BCP_];

static constexpr int SMEM_BYTES = TILE_E * BCP_ * 4 + TILE_E * 2 * 4; // 32KB + 1KB

// ---------------------------------------------------------------------------
// Transpose role: data[bc0..bc0+63][n0..n0+31] -> buf[n][64].  512 threads.
// ---------------------------------------------------------------------------
__device__ __forceinline__
void transpose_role(const float* __restrict__ data, float* __restrict__ buf,
                    int bc0, int tileIdx, char* smem) {
    float (*tile)[33] = reinterpret_cast<float (*)[33]>(smem);   // [64][33]
    const int t    = threadIdx.x;
    const int lane = t & 31;
    const int w    = t >> 5;                    // 0..15
    const int n0   = tileIdx * TILE_N;

    #pragma unroll
    for (int k = 0; k < 4; ++k) {
        const int row = k * 16 + w;             // bc within slice, 0..63
        tile[row][lane] = __ldcs(&data[(size_t)(bc0 + row) * N_ + n0 + lane]);
    }
    __syncthreads();

    // write buf[n0+nl][*] as float4 over bc: 16 float4 per n row, 32 n rows
    const int nl = t >> 4;                      // 0..31
    const int c4 = t & 15;                      // bc float4 0..15
    float4 v;
    v.x = tile[4 * c4 + 0][nl];
    v.y = tile[4 * c4 + 1][nl];
    v.z = tile[4 * c4 + 2][nl];
    v.w = tile[4 * c4 + 3][nl];
    reinterpret_cast<float4*>(buf)[(size_t)(n0 + nl) * BCP4_ + c4] = v;
}

// ---------------------------------------------------------------------------
// Gather role: zero-head chunk + up to 128-edge tile for one 64-bc slice.
// SMEM mid (el, bc): word = el*64 + 4*((bc>>2) ^ ((el>>2)&15)) + (bc&3).
// Phase-A float4 stores and phase-B column reads both bank-conflict-free.
// ---------------------------------------------------------------------------
__device__ __forceinline__
void gather_role(const int* __restrict__ edges, float* __restrict__ out,
                 const float* __restrict__ buf, int bc0, int tileIdx,
                 char* smem) {
    float* mid   = reinterpret_cast<float*>(smem);
    int*   sedge = reinterpret_cast<int*>(smem + TILE_E * BCP_ * 4);

    const int t  = threadIdx.x;
    const int e0 = tileIdx * TILE_E;
    const int nE = (E_ - e0 < TILE_E) ? (E_ - e0) : TILE_E;

    // fused zero head: 64 rows * 25000 float4 = 1.6M over 1563 tiles
    {
        const float4 z = make_float4(0.f, 0.f, 0.f, 0.f);
        float4* __restrict__ o4 = reinterpret_cast<float4*>(out);
        #pragma unroll
        for (int k = 0; k < 2; ++k) {
            const int idx = tileIdx * 1024 + k * 512 + t;
            if (idx < BCP_ * N4_) {
                const int bcl = idx / N4_;
                const int j4  = idx - bcl * N4_;
                __stcs(&o4[(size_t)(bc0 + bcl) * M4_ + j4], z);
            }
        }
    }

    if (t < 2 * nE) sedge[t] = __ldg(&edges[e0 * 2 + t]);
    __syncthreads();

    // phase A: float4 gather-average from L2-resident scratch
    const int q = t >> 4;                        // edge slot 0..31
    const int m = t & 15;                        // bc float4 0..15
    const float4* __restrict__ dT4 = reinterpret_cast<const float4*>(buf);
    float4* __restrict__ mid4 = reinterpret_cast<float4*>(mid);

    #pragma unroll
    for (int it = 0; it < 4; ++it) {
        const int el = it * 32 + q;
        if (el < nE) {
            const int p0 = sedge[2 * el];
            const int p1 = sedge[2 * el + 1];
            const float4 a = __ldg(&dT4[(size_t)p0 * BCP4_ + m]);
            const float4 b = __ldg(&dT4[(size_t)p1 * BCP4_ + m]);
            float4 r;
            r.x = (a.x + b.x) * 0.5f;
            r.y = (a.y + b.y) * 0.5f;
            r.z = (a.z + b.z) * 0.5f;
            r.w = (a.w + b.w) * 0.5f;
            mid4[el * BCP4_ + (m ^ ((el >> 2) & 15))] = r;
        }
    }
    __syncthreads();

    // phase B: transpose-on-write, 128B coalesced streaming stores
    const int w   = t >> 5;
    const int l   = t & 31;
    const int j   = l & 7;
    const int bcl = w * 4 + (l >> 3);            // 0..63
    const int g4  = bcl >> 2;                    // == w (warp-constant)
    const int b3  = bcl & 3;
    float4* __restrict__ dst =
        reinterpret_cast<float4*>(out + (size_t)(bc0 + bcl) * M_);
    #pragma unroll
    for (int h = 0; h < 4; ++h) {
        const int jj = j + 8 * h;                // float4 span 0..31
        if (jj * 4 < nE) {
            float4 r;
            r.x = mid[(4 * jj + 0) * BCP_ + 4 * (g4 ^ (jj & 15)) + b3];
            r.y = mid[(4 * jj + 1) * BCP_ + 4 * (g4 ^ (jj & 15)) + b3];
            r.z = mid[(4 * jj + 2) * BCP_ + 4 * (g4 ^ (jj & 15)) + b3];
            r.w = mid[(4 * jj + 3) * BCP_ + 4 * (g4 ^ (jj & 15)) + b3];
            __stcs(&dst[N4_ + (e0 >> 2) + jj], r);
        }
    }
}

// ---------------------------------------------------------------------------
// Fused pipelined kernel: CTAs [0, nGather) gather slice from bufG;
// CTAs [nGather, nGather+nTrans) transpose next slice into bufT.
// ---------------------------------------------------------------------------
__global__ __launch_bounds__(512)
void fused_kernel(const float* __restrict__ data,
                  const int*   __restrict__ edges,
                  float*       __restrict__ out,
                  int nGather, int gat_bc0, int bufG_idx,
                  int trn_bc0, int bufT_idx) {
    __shared__ __align__(16) char smem[SMEM_BYTES];   // 33 KB union

    if ((int)blockIdx.x < nGather) {
        gather_role(edges, out, g_scratch[bufG_idx], gat_bc0,
                    blockIdx.x, smem);
    } else {
        transpose_role(data, g_scratch[bufT_idx], trn_bc0,
                       blockIdx.x - nGather, smem);
    }
}

extern "C" void kernel_launch(void* const* d_in, const int* in_sizes, int n_in,
                              void* d_out, int out_size) {
    const float* data  = (const float*)d_in[0];
    const int*   edges = (const int*)d_in[1];
    float*       out   = (float*)d_out;

    // Prologue: transpose slice 0 -> buf0
    fused_kernel<<<NTTILE, 512>>>(data, edges, out,
                                  /*nGather=*/0, 0, 0,
                                  /*trn_bc0=*/0, /*bufT=*/0);
    // Pipelined passes: gather slice p (buf p&1) + transpose slice p+1
    for (int p = 0; p < NPASS - 1; ++p) {
        fused_kernel<<<NGTILE + NTTILE, 512>>>(data, edges, out,
                                               NGTILE, p * BCP_, p & 1,
                                               (p + 1) * BCP_, (p + 1) & 1);
    }
    // Epilogue: gather last slice only
    fused_kernel<<<NGTILE, 512>>>(data, edges, out,
                                  NGTILE, (NPASS - 1) * BCP_, (NPASS - 1) & 1,
                                  0, 0);
}